// round 11
// baseline (speedup 1.0000x reference)
#include <cuda_runtime.h>
#include <cuda_fp16.h>
#include <math.h>
#include <stdint.h>

#define B_   2
#define N_   4
#define T_   1024
#define D_   512
#define E_   16
#define KX   15          // computed experts (1..15)
#define DFFN 828
#define ND   2048        // N_*D_
#define MTOK 2048        // B_*T_
#define KSPLIT 32        // split-K factor for MHC projection

// ---------------- scratch (device globals; no allocation) ----------------
__device__ float g_xn[MTOK * ND];
__device__ int   g_cnt[KX];
__device__ int   g_idx[KX][MTOK];
__device__ int   g_pos[KX][MTOK];
__device__ float g_rs[(long)KX * 16 * 24 * KSPLIT * 128];
__device__ float g_Hpre[KX][MTOK][4];
__device__ float g_Hpost[KX][MTOK][4];
__device__ float g_Hres[KX][MTOK][16];
__device__ float g_gate[KX][MTOK];
// pair-split fp16 buffers: 1 u32 per element (hi halves | lo halves interleaved by k-pair)
__device__ unsigned int g_h [(long)KX * MTOK * D_];
__device__ unsigned int g_s1[(long)KX * MTOK * D_];
__device__ unsigned int g_t2[(long)KX * MTOK * DFFN];
// raw fp32 buffers
__device__ float g_gsig[(long)KX * MTOK * D_];
__device__ float g_t1[(long)KX * MTOK * DFFN];
__device__ float g_oute[(long)KX * MTOK * D_];
// pair-split weights (experts 1..15), same byte size as fp32 originals
__device__ unsigned int g_wd_p [(long)KX * D_ * D_];
__device__ unsigned int g_wu_p [(long)KX * D_ * D_];
__device__ unsigned int g_wg_p [(long)KX * DFFN * D_];
__device__ unsigned int g_wup_p[(long)KX * DFFN * D_];
__device__ unsigned int g_wdn_p[(long)KX * D_ * DFFN];

__device__ __forceinline__ float sigmoidf_(float x) { return 1.f / (1.f + expf(-x)); }

// split float2 (consecutive k pair) -> fp16 hi pair u32, fp16 lo pair u32
__device__ __forceinline__ void split_h2(float2 v, uint32_t& hi, uint32_t& lo) {
    __half2 h = __float22half2_rn(v);
    float2 back = __half22float2(h);
    __half2 l = __float22half2_rn(make_float2(v.x - back.x, v.y - back.y));
    hi = *(uint32_t*)&h;
    lo = *(uint32_t*)&l;
}

__device__ __forceinline__ float block_reduce_sum(float v, float* sbuf) {
    int tid = threadIdx.x;
    #pragma unroll
    for (int o = 16; o > 0; o >>= 1) v += __shfl_down_sync(0xffffffffu, v, o);
    if ((tid & 31) == 0) sbuf[tid >> 5] = v;
    __syncthreads();
    int nw = blockDim.x >> 5;
    float r = (tid < nw) ? sbuf[tid] : 0.f;
    if (tid < 32) {
        #pragma unroll
        for (int o = 16; o > 0; o >>= 1) r += __shfl_down_sync(0xffffffffu, r, o);
        if (tid == 0) sbuf[0] = r;
    }
    __syncthreads();
    return sbuf[0];
}

// ---------------- weight split into pair format ---------------------------
__global__ void wsplit_kernel(const float* __restrict__ src,
                              unsigned int* __restrict__ dst, long n)
{
    long i = ((long)blockIdx.x * 256 + threadIdx.x) * 4;
    if (i >= n) return;
    float4 v = *(const float4*)(src + i);
    uint4 o;
    split_h2(make_float2(v.x, v.y), o.x, o.y);
    split_h2(make_float2(v.z, v.w), o.z, o.w);
    *(uint4*)(dst + i) = o;
}

// ---------------- K-1: zero per-expert counters ---------------------------
__global__ void zero_cnt_kernel() {
    if (threadIdx.x < KX) g_cnt[threadIdx.x] = 0;
}

// ---------------- K0: routing + compaction lists --------------------------
__global__ void routing_kernel(const float* __restrict__ stream,
                               const float* __restrict__ router_w,
                               float* __restrict__ out)
{
    int t = blockIdx.x;
    int b = t >> 10, tt = t & 1023;
    int tid = threadIdx.x;           // 128
    __shared__ float sred[E_][128];

    float acc[E_];
    #pragma unroll
    for (int e = 0; e < E_; e++) acc[e] = 0.f;

    for (int d = tid; d < D_; d += 128) {
        float ri = 0.f;
        #pragma unroll
        for (int n = 0; n < N_; n++)
            ri += stream[(((long)(b * N_ + n)) * T_ + tt) * D_ + d];
        ri *= 0.25f;
        #pragma unroll
        for (int e = 0; e < E_; e++) acc[e] += ri * router_w[e * D_ + d];
    }
    #pragma unroll
    for (int e = 0; e < E_; e++) sred[e][tid] = acc[e];
    __syncthreads();
    for (int s = 64; s > 0; s >>= 1) {
        if (tid < s) {
            #pragma unroll
            for (int e = 0; e < E_; e++) sred[e][tid] += sred[e][tid + s];
        }
        __syncthreads();
    }

    if (tid == 0) {
        float probs[E_];
        float mx = -1e30f;
        for (int e = 0; e < E_; e++) mx = fmaxf(mx, sred[e][0]);
        float ssum = 0.f;
        for (int e = 0; e < E_; e++) { probs[e] = expf(sred[e][0] - mx); ssum += probs[e]; }
        float inv = 1.f / ssum;
        for (int e = 0; e < E_; e++) probs[e] *= inv;

        int order[E_];
        for (int e = 0; e < E_; e++) order[e] = e;
        for (int i = 1; i < E_; i++) {
            int oi = order[i]; float p = probs[oi]; int j = i - 1;
            while (j >= 0 && probs[order[j]] < p) { order[j + 1] = order[j]; j--; }
            order[j + 1] = oi;
        }
        float gate[E_];
        for (int e = 0; e < E_; e++) gate[e] = 0.f;
        float cum = 0.f;
        for (int i = 0; i < E_; i++) {
            float p = probs[order[i]];
            bool m = (i == 0) || ((cum < 0.8f) && (i < 4));
            if (m) gate[order[i]] = p;
            cum += p;
        }
        float lp = 0.f;
        for (int e = 0; e < E_; e++)
            if (gate[e] > 0.f) lp += fmaxf(logf(probs[e]), -10.f);

        float* out_gate = out + (long)B_ * N_ * T_ * D_;
        float* out_lp   = out_gate + (long)B_ * T_ * E_;
        for (int e = 0; e < E_; e++) out_gate[(long)t * E_ + e] = gate[e];
        out_lp[t] = lp;
        for (int k = 0; k < KX; k++) {
            float gk = gate[k + 1];
            g_gate[k][t] = gk;
            if (gk > 0.f) {
                int p = atomicAdd(&g_cnt[k], 1);
                g_idx[k][p] = t;
                g_pos[k][t] = p;
            } else {
                g_pos[k][t] = -1;
            }
        }
    }
}

// ---------------- K1: xn = RMSNorm over nd of transposed stream ----------
__global__ void xn_kernel(const float* __restrict__ stream)
{
    int t = blockIdx.x;
    int b = t >> 10, tt = t & 1023;
    int tid = threadIdx.x;           // 256
    __shared__ float sbuf[32];
    float v[8]; float ss = 0.f;
    #pragma unroll
    for (int i = 0; i < 8; i++) {
        int j = tid + i * 256;
        int n = j >> 9, d = j & 511;
        float x = stream[(((long)(b * N_ + n)) * T_ + tt) * D_ + d];
        v[i] = x; ss += x * x;
    }
    float tot = block_reduce_sum(ss, sbuf);
    float rms = rsqrtf(tot * (1.f / ND) + 1e-8f);
    #pragma unroll
    for (int i = 0; i < 8; i++)
        g_xn[(long)t * ND + tid + i * 256] = v[i] * rms;
}

// ---------------- K2a: MHC projection partials (split-K) -----------------
__global__ __launch_bounds__(256) void mhc_part(
    const float* __restrict__ norm_w,
    const float* __restrict__ phi_pre, const float* __restrict__ phi_post,
    const float* __restrict__ phi_res)
{
    int tile = blockIdx.x;
    int k = blockIdx.y; int e = k + 1;
    int ks = blockIdx.z;
    int t0 = tile * 128;
    int cnt = g_cnt[k];
    if (t0 >= cnt) return;
    int tid = threadIdx.x;

    __shared__ int   tok[128];
    __shared__ float xs[32][129];
    __shared__ float ws[32][25];

    if (tid < 128) {
        int s = t0 + tid;
        tok[tid] = (s < cnt) ? g_idx[k][s] : g_idx[k][0];
    }
    __syncthreads();

    int r = tid & 63;
    int q = tid >> 6;

    float acc[2][6];
    #pragma unroll
    for (int a = 0; a < 2; a++)
        #pragma unroll
        for (int m = 0; m < 6; m++) acc[a][m] = 0.f;

    const int kbeg = ks * (ND / KSPLIT);
    const int kend = kbeg + (ND / KSPLIT);
    for (int kb = kbeg; kb < kend; kb += 32) {
        #pragma unroll
        for (int i = 0; i < 16; i++) {
            int lin = tid + i * 256;
            int trow = lin >> 5, tcol = lin & 31;
            xs[tcol][trow] = g_xn[(long)tok[trow] * ND + kb + tcol];
        }
        #pragma unroll
        for (int i = 0; i < 3; i++) {
            int lin = tid + i * 256;
            int jrow = lin >> 5, kcol = lin & 31;
            int gk = kb + kcol;
            const float* wr;
            if (jrow < 4)      wr = phi_pre  + (long)(e * 4  + jrow)       * ND;
            else if (jrow < 8) wr = phi_post + (long)(e * 4  + (jrow - 4)) * ND;
            else               wr = phi_res  + (long)(e * 16 + (jrow - 8)) * ND;
            ws[kcol][jrow] = wr[gk] * norm_w[(long)e * ND + gk];
        }
        __syncthreads();
        #pragma unroll
        for (int kk = 0; kk < 32; kk++) {
            float x0 = xs[kk][r], x1 = xs[kk][r + 64];
            #pragma unroll
            for (int m = 0; m < 6; m++) {
                float w = ws[kk][q + m * 4];
                acc[0][m] += x0 * w;
                acc[1][m] += x1 * w;
            }
        }
        __syncthreads();
    }

    long base = ((long)(k * 16 + tile)) * 24;
    #pragma unroll
    for (int m = 0; m < 6; m++) {
        int j = q + m * 4;
        long o = ((base + j) * KSPLIT + ks) * 128;
        g_rs[o + r]      = acc[0][m];
        g_rs[o + r + 64] = acc[1][m];
    }
}

// ---------------- K2b: sum partials + sigmoid/sinkhorn epilogue ----------
__global__ void mhc_epi(
    const float* __restrict__ b_pre, const float* __restrict__ b_post,
    const float* __restrict__ b_res,
    const float* __restrict__ alpha_pre, const float* __restrict__ alpha_post,
    const float* __restrict__ alpha_res)
{
    int tile = blockIdx.x;
    int k = blockIdx.y; int e = k + 1;
    int cnt = g_cnt[k];
    int slot = tile * 128 + threadIdx.x;
    if (slot >= cnt) return;

    float rsv[24];
    long base = ((long)(k * 16 + tile)) * 24;
    #pragma unroll
    for (int j = 0; j < 24; j++) {
        long o = (base + j) * KSPLIT * 128 + threadIdx.x;
        float s = 0.f;
        #pragma unroll
        for (int ks = 0; ks < KSPLIT; ks++) s += g_rs[o + (long)ks * 128];
        rsv[j] = s;
    }

    float ap  = alpha_pre[e];
    float apo = alpha_post[e];
    float ar  = alpha_res[e];
    #pragma unroll
    for (int n = 0; n < 4; n++) {
        g_Hpre[k][slot][n]  = sigmoidf_(ap  * rsv[n]     + b_pre[e * 4 + n]);
        g_Hpost[k][slot][n] = 2.f * sigmoidf_(apo * rsv[4 + n] + b_post[e * 4 + n]);
    }
    float m[4][4];
    #pragma unroll
    for (int i = 0; i < 4; i++)
        #pragma unroll
        for (int j = 0; j < 4; j++)
            m[i][j] = expf(ar * rsv[8 + i * 4 + j] + b_res[e * 16 + i * 4 + j]);
    #pragma unroll
    for (int it = 0; it < 6; it++) {
        #pragma unroll
        for (int i = 0; i < 4; i++) {
            float s = m[i][0] + m[i][1] + m[i][2] + m[i][3];
            float iv = 1.f / s;
            m[i][0] *= iv; m[i][1] *= iv; m[i][2] *= iv; m[i][3] *= iv;
        }
        #pragma unroll
        for (int j = 0; j < 4; j++) {
            float s = m[0][j] + m[1][j] + m[2][j] + m[3][j];
            float iv = 1.f / s;
            m[0][j] *= iv; m[1][j] *= iv; m[2][j] *= iv; m[3][j] *= iv;
        }
    }
    #pragma unroll
    for (int i = 0; i < 4; i++)
        #pragma unroll
        for (int j = 0; j < 4; j++)
            g_Hres[k][slot][i * 4 + j] = m[i][j];
}

// ---------------- K3: h (pair-split) = RMSNorm(H_pre @ stream) * snw -----
__global__ void he_kernel(const float* __restrict__ stream,
                          const float* __restrict__ snw)
{
    int k = blockIdx.x;
    int slot = blockIdx.y;
    if (slot >= g_cnt[k]) return;
    int t = g_idx[k][slot];
    int b = t >> 10, tt = t & 1023;
    int tid = threadIdx.x;           // 128; each owns 4 consecutive d
    __shared__ float sbuf[32];

    float hp[4];
    #pragma unroll
    for (int n = 0; n < 4; n++) hp[n] = g_Hpre[k][slot][n];

    int d0 = tid * 4;
    float v[4] = {0.f, 0.f, 0.f, 0.f};
    #pragma unroll
    for (int n = 0; n < 4; n++) {
        float4 s4 = *(const float4*)(stream + (((long)(b * N_ + n)) * T_ + tt) * D_ + d0);
        v[0] += hp[n] * s4.x; v[1] += hp[n] * s4.y;
        v[2] += hp[n] * s4.z; v[3] += hp[n] * s4.w;
    }
    float ss = v[0]*v[0] + v[1]*v[1] + v[2]*v[2] + v[3]*v[3];
    float tot = block_reduce_sum(ss, sbuf);
    float rms = rsqrtf(tot * (1.f / D_) + 1e-8f);
    int e = k + 1;
    float4 w4 = *(const float4*)(snw + e * D_ + d0);
    float o0 = v[0] * rms * w4.x, o1 = v[1] * rms * w4.y;
    float o2 = v[2] * rms * w4.z, o3 = v[3] * rms * w4.w;
    uint4 p;
    split_h2(make_float2(o0, o1), p.x, p.y);
    split_h2(make_float2(o2, o3), p.z, p.w);
    *(uint4*)(g_h + ((long)k * MTOK + slot) * D_ + d0) = p;
}

// ---------------- pre-split fp16 mma.sync GEMM, cp.async pipeline --------
// C[M,N] = epi(A[M,Kd] @ W[N,Kd]^T); A,W in pair-split u32 format.
#define EPI_SILU    0
#define EPI_SIGMOID 1
#define EPI_MUL     2

__device__ __forceinline__ void mma_f16(float* c, const uint32_t* a, const uint32_t* b) {
    asm volatile(
        "mma.sync.aligned.m16n8k16.row.col.f32.f16.f16.f32 "
        "{%0,%1,%2,%3}, {%4,%5,%6,%7}, {%8,%9}, {%0,%1,%2,%3};"
        : "+f"(c[0]), "+f"(c[1]), "+f"(c[2]), "+f"(c[3])
        : "r"(a[0]), "r"(a[1]), "r"(a[2]), "r"(a[3]), "r"(b[0]), "r"(b[1]));
}

__device__ __forceinline__ void cp_async16(uint32_t dst, const void* src, int src_size) {
    asm volatile("cp.async.cg.shared.global [%0], [%1], 16, %2;"
                 :: "r"(dst), "l"(src), "r"(src_size) : "memory");
}
#define CP_COMMIT() asm volatile("cp.async.commit_group;" ::: "memory")
#define CP_WAIT(n)  asm volatile("cp.async.wait_group %0;" :: "n"(n) : "memory")

// smem: [row 0..127][16 u32 data + 8 pad], stride 24 u32 (conflict-free
// LDS.64: gid*24 mod 32 = {0,24,16,8}; +2*tig tiles all 32 banks).
#define GSTRIDE 24
#define GBUF    (128 * GSTRIDE)       // 3072 u32 = 12 KB
#define GT_SMEM (4 * GBUF * 4)        // A0|A1|B0|B1 = 48 KB

__device__ __forceinline__ void issue_tile(
    uint32_t addr, const unsigned int* P, int base, int N, int Kd, int kb,
    int tid, int guard)
{
    #pragma unroll
    for (int i = 0; i < 2; i++) {
        int c   = tid + i * 256;
        int row = c >> 2, k4 = c & 3;
        int kg  = kb + k4 * 4;                 // u32 index == element index
        int pr  = base + row;
        int pc  = (!guard || pr < N) ? pr : (N - 1);
        int ok  = ((!guard || pr < N) && kg < Kd) ? 16 : 0;   // Kd % 4 == 0
        cp_async16(addr + (uint32_t)(row * (GSTRIDE * 4) + k4 * 16),
                   P + (long)pc * Kd + kg, ok);
    }
}

__global__ __launch_bounds__(256) void sgemm_tc(
    const unsigned int* __restrict__ Abase, long sA,
    const unsigned int* __restrict__ Wbase, long sW,
    void* __restrict__ Cbase, long sC,
    const float* __restrict__ Xbase, long sX,
    int N, int Kd, int epi, int outSplit)
{
    int z = blockIdx.z;
    int Me = g_cnt[z];
    int rowBase = blockIdx.y * 128;
    if (rowBase >= Me) return;
    int colBase = blockIdx.x * 128;

    extern __shared__ __align__(16) unsigned int sdyn[];

    const unsigned int* A = Abase + (long)z * sA;
    const unsigned int* W = Wbase + (long)z * sW;
    const float* X = Xbase ? (Xbase + (long)z * sX) : nullptr;
    float*        Cf = (float*)Cbase + (long)z * sC;
    unsigned int* Cu = (unsigned int*)Cbase + (long)z * sC;

    int tid  = threadIdx.x;
    int wid  = tid >> 5, lane = tid & 31;
    int gid  = lane >> 2, tig = lane & 3;
    int warpM = wid & 3, warpN = wid >> 2;     // 4 x 2 warp grid
    int m0 = warpM * 32;
    int n0 = warpN * 64;

    uint32_t sbase;
    asm("{ .reg .u64 t; cvta.to.shared.u64 t, %1; cvt.u32.u64 %0, t; }"
        : "=r"(sbase) : "l"((const void*)sdyn));
    uint32_t aA0 = sbase, bA0 = sbase + 2 * GBUF * 4;

    float acc[2][8][4];
    #pragma unroll
    for (int i = 0; i < 2; i++)
        #pragma unroll
        for (int j = 0; j < 8; j++)
            #pragma unroll
            for (int q = 0; q < 4; q++) acc[i][j][q] = 0.f;

    int nstages = (Kd + 15) >> 4;
    int ko = 2 * tig;                           // u32 slot for k-pair tig

    issue_tile(aA0, A, rowBase, 1 << 30, Kd, 0, tid, 0);
    issue_tile(bA0, W, colBase, N, Kd, 0, tid, 1);
    CP_COMMIT();

    for (int st = 0; st < nstages; st++) {
        if (st + 1 < nstages) {
            int buf = (st + 1) & 1;
            issue_tile(aA0 + buf * GBUF * 4, A, rowBase, 1 << 30, Kd, (st + 1) << 4, tid, 0);
            issue_tile(bA0 + buf * GBUF * 4, W, colBase, N, Kd, (st + 1) << 4, tid, 1);
            CP_COMMIT();
            CP_WAIT(1);
        } else {
            CP_WAIT(0);
        }
        __syncthreads();

        const unsigned int* As = sdyn + (st & 1) * GBUF;
        const unsigned int* Bs = sdyn + 2 * GBUF + (st & 1) * GBUF;

        uint32_t aH[2][4], aL[2][4];
        #pragma unroll
        for (int mf = 0; mf < 2; mf++) {
            int mr0 = (m0 + mf * 16 + gid) * GSTRIDE;
            int mr1 = mr0 + 8 * GSTRIDE;
            uint2 p;
            p = *(const uint2*)(As + mr0 + ko);     aH[mf][0] = p.x; aL[mf][0] = p.y;
            p = *(const uint2*)(As + mr1 + ko);     aH[mf][1] = p.x; aL[mf][1] = p.y;
            p = *(const uint2*)(As + mr0 + ko + 8); aH[mf][2] = p.x; aL[mf][2] = p.y;
            p = *(const uint2*)(As + mr1 + ko + 8); aH[mf][3] = p.x; aL[mf][3] = p.y;
        }
        #pragma unroll
        for (int nf = 0; nf < 8; nf++) {
            int nr = (n0 + nf * 8 + gid) * GSTRIDE;
            uint2 q0 = *(const uint2*)(Bs + nr + ko);
            uint2 q1 = *(const uint2*)(Bs + nr + ko + 8);
            uint32_t bh[2] = {q0.x, q1.x};
            uint32_t bl[2] = {q0.y, q1.y};
            mma_f16(acc[0][nf], aH[0], bh);
            mma_f16(acc[1][nf], aH[1], bh);
            mma_f16(acc[0][nf], aL[0], bh);
            mma_f16(acc[1][nf], aL[1], bh);
            mma_f16(acc[0][nf], aH[0], bl);
            mma_f16(acc[1][nf], aH[1], bl);
        }
        __syncthreads();
    }

    // ---- epilogue: q pairs (0,1) and (2,3) are consecutive columns ----
    #pragma unroll
    for (int mf = 0; mf < 2; mf++) {
        #pragma unroll
        for (int nf = 0; nf < 8; nf++) {
            int cc0 = colBase + n0 + nf * 8 + 2 * tig;    // even; cc0+1 < N iff cc0 < N
            if (cc0 >= N) continue;
            #pragma unroll
            for (int hq = 0; hq < 2; hq++) {
                int rr = rowBase + m0 + mf * 16 + gid + hq * 8;
                if (rr >= Me) continue;
                float v0 = acc[mf][nf][2 * hq + 0];
                float v1 = acc[mf][nf][2 * hq + 1];
                long i0 = (long)rr * N + cc0;
                if (epi == EPI_SILU) {
                    v0 = v0 * (1.f / (1.f + expf(-v0)));
                    v1 = v1 * (1.f / (1.f + expf(-v1)));
                } else if (epi == EPI_SIGMOID) {
                    v0 = 1.f / (1.f + expf(-v0));
                    v1 = 1.f / (1.f + expf(-v1));
                } else {
                    v0 *= X[i0];
                    v1 *= X[i0 + 1];
                }
                if (outSplit) {
                    uint2 p;
                    split_h2(make_float2(v0, v1), p.x, p.y);
                    *(uint2*)(Cu + i0) = p;
                } else {
                    *(float2*)(Cf + i0) = make_float2(v0, v1);
                }
            }
        }
    }
}

// ---------------- K5: combine (res + post, gated sum over experts) -------
__global__ void combine_kernel(const float* __restrict__ stream,
                               float* __restrict__ out)
{
    int t = blockIdx.x;
    int b = t >> 10, tt = t & 1023;
    int tid = threadIdx.x;      // 256
    __shared__ float cres[16];
    __shared__ float pc[KX][4];
    __shared__ float gsh[KX];
    __shared__ int   posh[KX];

    if (tid < KX) {
        gsh[tid]  = g_gate[tid][t];
        posh[tid] = g_pos[tid][t];
    }
    __syncthreads();
    if (tid < 16) {
        float s = 0.f;
        for (int kk = 0; kk < KX; kk++) {
            int p = posh[kk];
            if (p >= 0) s += gsh[kk] * g_Hres[kk][p][tid];
        }
        cres[tid] = s;
    } else if (tid >= 32 && tid < 32 + KX * 4) {
        int idx = tid - 32; int kk = idx >> 2, i = idx & 3;
        int p = posh[kk];
        pc[kk][i] = (p >= 0) ? gsh[kk] * g_Hpost[kk][p][i] : 0.f;
    }
    __syncthreads();

    for (int d = tid; d < D_; d += 256) {
        float sj[4];
        #pragma unroll
        for (int j = 0; j < 4; j++)
            sj[j] = stream[(((long)(b * N_ + j)) * T_ + tt) * D_ + d];
        float r[4];
        #pragma unroll
        for (int i = 0; i < 4; i++)
            r[i] = cres[i * 4 + 0] * sj[0] + cres[i * 4 + 1] * sj[1]
                 + cres[i * 4 + 2] * sj[2] + cres[i * 4 + 3] * sj[3];
        for (int kk = 0; kk < KX; kk++) {
            int p = posh[kk];
            if (p >= 0) {
                float oe = g_oute[((long)kk * MTOK + p) * D_ + d];
                #pragma unroll
                for (int i = 0; i < 4; i++) r[i] += pc[kk][i] * oe;
            }
        }
        #pragma unroll
        for (int i = 0; i < 4; i++)
            out[(((long)(b * N_ + i)) * T_ + tt) * D_ + d] = r[i];
    }
}

// ---------------- launch ----------------
extern "C" void kernel_launch(void* const* d_in, const int* in_sizes, int n_in,
                              void* d_out, int out_size)
{
    const float* stream    = (const float*)d_in[0];
    const float* norm_w    = (const float*)d_in[1];
    const float* phi_pre   = (const float*)d_in[2];
    const float* phi_post  = (const float*)d_in[3];
    const float* phi_res   = (const float*)d_in[4];
    const float* b_pre     = (const float*)d_in[5];
    const float* b_post    = (const float*)d_in[6];
    const float* b_res     = (const float*)d_in[7];
    const float* alpha_pre = (const float*)d_in[8];
    const float* alpha_post= (const float*)d_in[9];
    const float* alpha_res = (const float*)d_in[10];
    const float* snw       = (const float*)d_in[11];
    const float* wd        = (const float*)d_in[12];
    const float* wu        = (const float*)d_in[13];
    const float* wg        = (const float*)d_in[14];
    const float* wup       = (const float*)d_in[15];
    const float* wdn       = (const float*)d_in[16];
    const float* rw        = (const float*)d_in[17];
    float* out = (float*)d_out;

    unsigned int *p_h, *p_s1, *p_t2;
    unsigned int *p_wd, *p_wu, *p_wg, *p_wup, *p_wdn;
    float *p_g, *p_t1, *p_oe;
    cudaGetSymbolAddress((void**)&p_h,   g_h);
    cudaGetSymbolAddress((void**)&p_s1,  g_s1);
    cudaGetSymbolAddress((void**)&p_t2,  g_t2);
    cudaGetSymbolAddress((void**)&p_g,   g_gsig);
    cudaGetSymbolAddress((void**)&p_t1,  g_t1);
    cudaGetSymbolAddress((void**)&p_oe,  g_oute);
    cudaGetSymbolAddress((void**)&p_wd,  g_wd_p);
    cudaGetSymbolAddress((void**)&p_wu,  g_wu_p);
    cudaGetSymbolAddress((void**)&p_wg,  g_wg_p);
    cudaGetSymbolAddress((void**)&p_wup, g_wup_p);
    cudaGetSymbolAddress((void**)&p_wdn, g_wdn_p);

    cudaFuncSetAttribute(sgemm_tc, cudaFuncAttributeMaxDynamicSharedMemorySize, GT_SMEM);

    // weight pre-split into pair format (same bytes as fp32; ~35 us)
    {
        long n1 = (long)KX * D_ * D_;
        long n2 = (long)KX * DFFN * D_;
        int  g1 = (int)((n1 + 1023) / 1024);
        int  g2 = (int)((n2 + 1023) / 1024);
        wsplit_kernel<<<g1, 256>>>(wd  + (long)D_ * D_,   p_wd,  n1);
        wsplit_kernel<<<g1, 256>>>(wu  + (long)D_ * D_,   p_wu,  n1);
        wsplit_kernel<<<g2, 256>>>(wg  + (long)DFFN * D_, p_wg,  n2);
        wsplit_kernel<<<g2, 256>>>(wup + (long)DFFN * D_, p_wup, n2);
        wsplit_kernel<<<g2, 256>>>(wdn + (long)D_ * DFFN, p_wdn, n2);
    }

    zero_cnt_kernel<<<1, 32>>>();
    routing_kernel<<<MTOK, 128>>>(stream, rw, out);
    xn_kernel<<<MTOK, 256>>>(stream);
    mhc_part<<<dim3(16, KX, KSPLIT), 256>>>(norm_w, phi_pre, phi_post, phi_res);
    mhc_epi<<<dim3(16, KX), 128>>>(b_pre, b_post, b_res,
                                   alpha_pre, alpha_post, alpha_res);
    he_kernel<<<dim3(KX, MTOK), 128>>>(stream, snw);

    long sHD = (long)MTOK * D_;
    long sHF = (long)MTOK * DFFN;

    // s1 = silu(h @ wd^T)                 [pair out]
    sgemm_tc<<<dim3(4, 16, KX), 256, GT_SMEM>>>(p_h, sHD, p_wd, (long)D_ * D_,
                                                p_s1, sHD, nullptr, 0,
                                                D_, D_, EPI_SILU, 1);
    // g = sigmoid(s1 @ wu^T)              [raw out]
    sgemm_tc<<<dim3(4, 16, KX), 256, GT_SMEM>>>(p_s1, sHD, p_wu, (long)D_ * D_,
                                                p_g, sHD, nullptr, 0,
                                                D_, D_, EPI_SIGMOID, 0);
    // t1 = silu(h @ gate^T)               [raw out]
    sgemm_tc<<<dim3(7, 16, KX), 256, GT_SMEM>>>(p_h, sHD, p_wg, (long)DFFN * D_,
                                                p_t1, sHF, nullptr, 0,
                                                DFFN, D_, EPI_SILU, 0);
    // t2 = (h @ up^T) * t1                [pair out]
    sgemm_tc<<<dim3(7, 16, KX), 256, GT_SMEM>>>(p_h, sHD, p_wup, (long)DFFN * D_,
                                                p_t2, sHF, p_t1, sHF,
                                                DFFN, D_, EPI_MUL, 1);
    // out_e = (t2 @ down^T) * g           [raw out]
    sgemm_tc<<<dim3(4, 16, KX), 256, GT_SMEM>>>(p_t2, sHF, p_wdn, (long)D_ * DFFN,
                                                p_oe, sHD, p_g, sHD,
                                                D_, DFFN, EPI_MUL, 0);

    combine_kernel<<<MTOK, 256>>>(stream, out);
}